// round 5
// baseline (speedup 1.0000x reference)
#include <cuda_runtime.h>
#include <cstdint>

#define NXg   240
#define NPAD  256
#define CN    8      // cluster size (CTAs)
#define RPC   30     // rows per CTA
#define NTH   480    // 15 warps, 2 rows each
#define NW    15
#define FFACf 0.4f
#define OMFf  0.6f

struct __align__(16) Smem {
    alignas(16) unsigned long long mbar[2];   // ping-pong cluster barriers (count=8)
    alignas(16) float udirs[32];
    alignas(16) float part[NW][12];           // per-warp 9 scalar partials (12 = 48B stride)
    alignas(16) float wred2[NW + 1][2];       // 16*2 floats = 128B
    alignas(16) float redF[CN][2];            // final-energy cluster slots
    alignas(16) float redslot[2][CN][16];     // ping-pong scalar slots [parity][src][scal]
    alignas(16) float uho [NPAD];
    alignas(16) float wbuf [2][2][NPAD];      // ping-pong wavefunctions (local)
    alignas(16) float fball[2][2][NPAD];      // ping-pong broadcast fb vectors (DSMEM-filled)
    alignas(16) float kin [RPC][NPAD];
    alignas(16) float vint[RPC][NPAD];
};

__device__ __forceinline__ uint32_t smem_u32(const void* p) {
    return (uint32_t)__cvta_generic_to_shared(p);
}
__device__ __forceinline__ void st_cluster_f32(uint32_t laddr, int rank, float v) {
    uint32_t r;
    asm volatile("mapa.shared::cluster.u32 %0, %1, %2;" : "=r"(r) : "r"(laddr), "r"(rank));
    asm volatile("st.shared::cluster.u32 [%0], %1;" :: "r"(r), "r"(__float_as_uint(v)) : "memory");
}
__device__ __forceinline__ void mbar_arrive_remote(uint32_t laddr, int rank) {
    asm volatile("{\n\t.reg .b32 ra;\n\t"
        "mapa.shared::cluster.u32 ra, %0, %1;\n\t"
        "mbarrier.arrive.release.cluster.shared::cluster.b64 _, [ra];\n\t}"
        :: "r"(laddr), "r"(rank) : "memory");
}
__device__ __forceinline__ void mbar_wait_parity(uint32_t addr, uint32_t parity) {
    uint32_t done;
    asm volatile("{\n\t.reg .pred p;\n\t"
        "mbarrier.try_wait.parity.acquire.cluster.shared::cta.b64 p, [%1], %2;\n\t"
        "selp.b32 %0, 1, 0, p;\n\t}"
        : "=r"(done) : "r"(addr), "r"(parity) : "memory");
    if (!done) {
        asm volatile("{\n\t.reg .pred P1;\n\t"
            "W_%=:\n\t"
            "mbarrier.try_wait.parity.acquire.cluster.shared::cta.b64 P1, [%0], %1, 0x989680;\n\t"
            "@P1 bra.uni D_%=;\n\t"
            "bra.uni W_%=;\n\t"
            "D_%=:\n\t}"
            :: "r"(addr), "r"(parity) : "memory");
    }
}
#define CLUSTER_SYNC() do { \
    asm volatile("barrier.cluster.arrive.aligned;" ::: "memory"); \
    asm volatile("barrier.cluster.wait.aligned;"   ::: "memory"); \
} while (0)

__device__ __forceinline__ float wred(float v) {
    v += __shfl_xor_sync(0xFFFFFFFFu, v, 16);
    v += __shfl_xor_sync(0xFFFFFFFFu, v, 8);
    v += __shfl_xor_sync(0xFFFFFFFFu, v, 4);
    v += __shfl_xor_sync(0xFFFFFFFFu, v, 2);
    v += __shfl_xor_sync(0xFFFFFFFFu, v, 1);
    return v;
}

// ---- packed f32x2 helpers (FFMA2 path, PTX-only) ----
__device__ __forceinline__ unsigned long long mul2(unsigned long long a, unsigned long long b) {
    unsigned long long d;
    asm("mul.rn.f32x2 %0, %1, %2;" : "=l"(d) : "l"(a), "l"(b));
    return d;
}
__device__ __forceinline__ unsigned long long fma2(unsigned long long a, unsigned long long b,
                                                   unsigned long long c) {
    unsigned long long d;
    asm("fma.rn.f32x2 %0, %1, %2, %3;" : "=l"(d) : "l"(a), "l"(b), "l"(c));
    return d;
}
__device__ __forceinline__ float hadd2(unsigned long long a) {
    uint32_t lo, hi;
    asm("mov.b64 {%0, %1}, %2;" : "=r"(lo), "=r"(hi) : "l"(a));
    return __uint_as_float(lo) + __uint_as_float(hi);
}
__device__ __forceinline__ float dot4p(const unsigned long long* k, const unsigned long long* x) {
    unsigned long long acc = mul2(k[0], x[0]);
    acc = fma2(k[1], x[1], acc);
    acc = fma2(k[2], x[2], acc);
    acc = fma2(k[3], x[3], acc);
    return hadd2(acc);
}
__device__ __forceinline__ void ld2x2(const float* p, int c1, int c2, unsigned long long* o) {
    ulonglong2 t0 = *reinterpret_cast<const ulonglong2*>(p + c1);
    ulonglong2 t1 = *reinterpret_cast<const ulonglong2*>(p + c2);
    o[0] = t0.x; o[1] = t0.y; o[2] = t1.x; o[3] = t1.y;
}

__global__ void __launch_bounds__(NTH, 1) __cluster_dims__(CN, 1, 1)
hf_kernel(const float* __restrict__ wfy0, const float* __restrict__ kin,
          const float* __restrict__ vint, const float* __restrict__ uho,
          const float* __restrict__ delx_p, const float* __restrict__ pfac_p,
          const int* __restrict__ iter_p, float* __restrict__ out)
{
    extern __shared__ char smraw[];
    Smem* s = reinterpret_cast<Smem*>(smraw);
    const int tid  = threadIdx.x;
    const int wid  = tid >> 5;
    const int lane = tid & 31;
    uint32_t rank;
    asm("mov.u32 %0, %%cluster_ctarank;" : "=r"(rank));
    const int row0 = (int)rank * RPC;
    const float delx = *delx_p;
    const float pfac = *pfac_p;
    const float rdelx = 1.f / delx;
    const int itermax = *iter_p;

    // ---- init ----
    if (tid == 0) {
        asm volatile("mbarrier.init.shared.b64 [%0], %1;" :: "r"(smem_u32(&s->mbar[0])), "r"(CN) : "memory");
        asm volatile("mbarrier.init.shared.b64 [%0], %1;" :: "r"(smem_u32(&s->mbar[1])), "r"(CN) : "memory");
    }
    for (int i = tid; i < RPC * NPAD; i += NTH) {
        int r = i >> 8, c = i & 255;
        s->kin [r][c] = (c < NXg) ? kin [(row0 + r) * NXg + c] : 0.f;
        s->vint[r][c] = (c < NXg) ? vint[(row0 + r) * NXg + c] : 0.f;
    }
    for (int c = tid; c < NPAD; c += NTH) {
        float a = (c < NXg) ? wfy0[c * 2 + 0] : 0.f;
        float b = (c < NXg) ? wfy0[c * 2 + 1] : 0.f;
        s->wbuf[0][0][c] = a;   s->wbuf[0][1][c] = b;
        s->wbuf[1][0][c] = 0.f; s->wbuf[1][1][c] = 0.f;
        s->uho[c] = (c < NXg) ? uho[c] : 0.f;
    }
    __syncthreads();
    CLUSTER_SYNC();   // mbar init visible cluster-wide

    // lane column ownership: [4l,4l+4) and [128+4l,128+4l+4)  (conflict-free LDS.128)
    const int c1 = lane * 4;
    const int c2 = 128 + lane * 4;
    const int r0 = wid * 2, r1 = r0 + 1;

    for (int it = 0; it < itermax; ++it) {
        const int cur = it & 1, nx = cur ^ 1;
        const float* w0 = s->wbuf[cur][0];
        const float* w1 = s->wbuf[cur][1];

        // RHS in packed pairs: A=w0, B=w1, C=w0*w0, D=w0*w1, E=w1*w1
        unsigned long long A[4], B[4], C[4], D[4], E[4];
        ld2x2(w0, c1, c2, A);
        ld2x2(w1, c1, c2, B);
        #pragma unroll
        for (int i = 0; i < 4; ++i) {
            C[i] = mul2(A[i], A[i]);
            D[i] = mul2(A[i], B[i]);
            E[i] = mul2(B[i], B[i]);
        }

        // ---- phase A: both rows fully, 10 interleaved wred chains ----
        unsigned long long K0[4], V0[4], K1[4], V1[4];
        ld2x2(s->kin[r0],  c1, c2, K0);
        ld2x2(s->vint[r0], c1, c2, V0);
        ld2x2(s->kin[r1],  c1, c2, K1);
        ld2x2(s->vint[r1], c1, c2, V1);
        float akw0 = dot4p(K0, A), akw1 = dot4p(K0, B);
        float av00 = dot4p(V0, C), av01 = dot4p(V0, D), av11 = dot4p(V0, E);
        float bkw0 = dot4p(K1, A), bkw1 = dot4p(K1, B);
        float bv00 = dot4p(V1, C), bv01 = dot4p(V1, D), bv11 = dot4p(V1, E);
        akw0 = wred(akw0); akw1 = wred(akw1);
        av00 = wred(av00); av01 = wred(av01); av11 = wred(av11);
        bkw0 = wred(bkw0); bkw1 = wred(bkw1);
        bv00 = wred(bv00); bv01 = wred(bv01); bv11 = wred(bv11);

        float p0=0,p1=0,p2=0,p3=0,p4=0,p5=0,p6=0,p7=0,p8=0;
        #pragma unroll
        for (int rr = 0; rr < 2; ++rr) {
            int r  = rr ? r1 : r0;
            float kw0 = rr ? bkw0 : akw0, kw1 = rr ? bkw1 : akw1;
            float v00 = rr ? bv00 : av00, v01 = rr ? bv01 : av01, v11 = rr ? bv11 : av11;
            int gi = row0 + r;
            float w0i = w0[gi], w1i = w1[gi], uh = s->uho[gi];   // broadcast LDS
            float ud  = delx * (v00 + v11);
            float hw0 = kw0 - delx * (w0i * v00 + w1i * v01) + (ud + uh) * w0i;
            float hw1 = kw1 - delx * (w0i * v01 + w1i * v11) + (ud + uh) * w1i;
            float fb0 = w0i - pfac * hw0;
            float fb1 = w1i - pfac * hw1;
            if (lane < CN) {
                st_cluster_f32(smem_u32(&s->fball[cur][0][gi]), lane, fb0);
                st_cluster_f32(smem_u32(&s->fball[cur][1][gi]), lane, fb1);
            }
            if (lane == 0) {
                s->udirs[r] = ud;
                p0 = fmaf(fb0, fb0, p0);  p1 = fmaf(fb1, fb1, p1);
                p2 = fmaf(fb0, fb1, p2);  p3 = fmaf(w0i, fb1, p3);
                p4 = fmaf(fb0, w0i, p4);  p5 = fmaf(w0i, w0i, p5);
                p6 = fmaf(w1i, w1i, p6);  p7 = fmaf(w1i, fb1, p7);
                p8 = fmaf(w0i * w0i + w1i * w1i, uh, p8);
            }
        }
        if (lane == 0) {
            float* pw = s->part[wid];
            pw[0]=p0; pw[1]=p1; pw[2]=p2; pw[3]=p3; pw[4]=p4;
            pw[5]=p5; pw[6]=p6; pw[7]=p7; pw[8]=p8;
        }
        __syncthreads();                                  // bar1

        // ---- warp 0: reduce 9 scalars over 15 warps, scatter + arrive ----
        if (wid == 0) {
            float v = 0.f;
            if (lane < 9) {
                #pragma unroll
                for (int w = 0; w < NW; ++w) v += s->part[w][lane];
            }
            float sv[9];
            #pragma unroll
            for (int j = 0; j < 9; ++j) sv[j] = __shfl_sync(0xFFFFFFFFu, v, j);
            if (lane < CN) {
                #pragma unroll
                for (int j = 0; j < 9; ++j)
                    st_cluster_f32(smem_u32(&s->redslot[cur][rank][j]), lane, sv[j]);
                mbar_arrive_remote(smem_u32(&s->mbar[cur]), lane);   // release covers this lane's stores
            }
        }
        mbar_wait_parity(smem_u32(&s->mbar[cur]), (uint32_t)((it >> 1) & 1));

        // ---- phase B: every thread redundantly combines scalars + updates w ----
        if (tid < NXg) {
            float S0=0,S1=0,Xs=0,Ys=0,Zs=0,W2=0;
            #pragma unroll
            for (int rr = 0; rr < CN; ++rr) {
                const float* q = s->redslot[cur][rr];
                S0 += q[0]; S1 += q[1]; Xs += q[2];
                Ys += q[3]; Zs += q[4]; W2 += q[5];
            }
            float inv0 = rsqrtf(S0 * delx);
            float inv1 = rsqrtf(S1 * delx);
            float dGS  = FFACf * inv0 * inv1 * Xs + OMFf * inv1 * Ys;
            float sn0  = 0.16f * rdelx + 0.48f * inv0 * Zs + 0.36f * W2;
            float T1   = rdelx - dGS * dGS * delx * (2.f - delx * sn0);
            float invT1d = __fdividef(1.f, T1 * delx);
            float a0 = FFACf * inv0;
            float b1 = FFACf * invT1d * inv1;
            float cc = FFACf * invT1d * dGS * delx;
            float fb0 = s->fball[cur][0][tid];
            float fb1 = s->fball[cur][1][tid];
            float n0 = a0 * fb0 + OMFf * w0[tid];
            float n1 = b1 * fb1 - cc * n0 + OMFf * w1[tid];
            s->wbuf[nx][0][tid] = n0;
            s->wbuf[nx][1][tid] = n1;
        }
        __syncthreads();                                  // bar2
    }

    // ---- final energies: ekin = new.K.new, epot = new.Umf.new ----
    {
        const int fin = itermax & 1, oldp = fin ^ 1, last = (itermax - 1) & 1;
        const float* wo0 = s->wbuf[oldp][0]; const float* wo1 = s->wbuf[oldp][1];
        const float* nv0 = s->wbuf[fin][0];  const float* nv1 = s->wbuf[fin][1];
        unsigned long long Ao[4], Bo[4], N0[4], N1[4], P0[4], P1[4], Q0[4], Q1[4];
        ld2x2(wo0, c1, c2, Ao);
        ld2x2(wo1, c1, c2, Bo);
        ld2x2(nv0, c1, c2, N0);
        ld2x2(nv1, c1, c2, N1);
        #pragma unroll
        for (int i = 0; i < 4; ++i) {
            P0[i] = mul2(Ao[i], N0[i]);
            P1[i] = mul2(Bo[i], N0[i]);
            Q0[i] = mul2(Ao[i], N1[i]);
            Q1[i] = mul2(Bo[i], N1[i]);
        }
        float pek = 0.f, pep = 0.f;
        for (int r = wid; r < RPC; r += NW) {
            unsigned long long K[4], V[4];
            ld2x2(s->kin[r],  c1, c2, K);
            ld2x2(s->vint[r], c1, c2, V);
            float kn0 = dot4p(K, N0), kn1 = dot4p(K, N1);
            float q00 = dot4p(V, P0), q10 = dot4p(V, P1);
            float q01 = dot4p(V, Q0), q11 = dot4p(V, Q1);
            kn0 = wred(kn0); kn1 = wred(kn1);
            q00 = wred(q00); q10 = wred(q10);
            q01 = wred(q01); q11 = wred(q11);
            if (lane == 0) {
                int gi = row0 + r;
                float n0i = nv0[gi], n1i = nv1[gi];
                float w0o = wo0[gi], w1o = wo1[gi];
                float diag = s->udirs[r] + s->uho[gi];
                float um0 = -delx * (w0o * q00 + w1o * q10) + diag * n0i;
                float um1 = -delx * (w0o * q01 + w1o * q11) + diag * n1i;
                pek += n0i * kn0 + n1i * kn1;
                pep += n0i * um0 + n1i * um1;
            }
        }
        if (lane == 0) { s->wred2[wid][0] = pek; s->wred2[wid][1] = pep; }
        __syncthreads();
        if (tid < 2) {
            float v = 0.f;
            #pragma unroll
            for (int w = 0; w < NW; ++w) v += s->wred2[w][tid];
            uint32_t la = smem_u32(&s->redF[rank][tid]);
            #pragma unroll
            for (int tr = 0; tr < CN; ++tr) st_cluster_f32(la, tr, v);
        }
        CLUSTER_SYNC();
        if (rank == 0 && tid == 0) {
            float EK = 0.f, EP = 0.f;
            for (int rr = 0; rr < CN; ++rr) { EK += s->redF[rr][0]; EP += s->redF[rr][1]; }
            float Zs=0,W2=0,V2=0,Us=0,EH=0;
            for (int rr = 0; rr < CN; ++rr) {
                const float* q = s->redslot[last][rr];
                Zs += q[4]; W2 += q[5]; V2 += q[6]; Us += q[7]; EH += q[8];
            }
            float esum = ((W2 - Zs) + (V2 - Us)) / pfac * delx;
            float eho  = EH * delx * 0.5f;
            float ekin = EK * delx;
            float epot = EP * delx;
            float enerhfp = (esum + ekin) * 0.5f + eho;
            float epot0   = epot - 2.f * eho;
            float enerhf  = esum - epot0 * 0.5f;
            out[0] = enerhf; out[1] = enerhfp; out[2] = ekin;
            out[3] = eho;    out[4] = epot0;   out[5] = esum;
        }
    }
}

extern "C" void kernel_launch(void* const* d_in, const int* in_sizes, int n_in,
                              void* d_out, int out_size) {
    (void)in_sizes; (void)n_in; (void)out_size;
    cudaFuncSetAttribute(hf_kernel, cudaFuncAttributeMaxDynamicSharedMemorySize,
                         (int)sizeof(Smem));
    hf_kernel<<<CN, NTH, sizeof(Smem)>>>(
        (const float*)d_in[0],   // wfy0 (240,2)
        (const float*)d_in[1],   // kin_mat (240,240)
        (const float*)d_in[2],   // Vint (240,240)
        (const float*)d_in[3],   // U_HO (240)
        (const float*)d_in[4],   // delx
        (const float*)d_in[5],   // pfac
        (const int*)d_in[6],     // itermax
        (float*)d_out);          // 6 outputs
}

// round 6
// speedup vs baseline: 1.2380x; 1.2380x over previous
#include <cuda_runtime.h>
#include <cstdint>

#define NXg   240
#define NPAD  256
#define CN    8      // cluster size (CTAs)
#define RPC   30     // rows per CTA
#define RPAD  32     // padded row count (rows 30,31 zero)
#define NTH   256    // 8 warps
#define NW    8
#define FFACf 0.4f
#define OMFf  0.6f

typedef unsigned long long ull;

struct __align__(16) Smem {
    alignas(16) ull   mbar[2];            // ping-pong cluster barriers (count=8)
    alignas(16) float scal[12];           // 9 global scalars (per-CTA replicated)
    alignas(16) float udirs[32];
    alignas(16) float wred2[NW][2];
    alignas(16) float redF[CN][2];        // final-energy cluster slots
    alignas(16) float uho [NPAD];
    alignas(16) float wbuf [2][2][NPAD];  // ping-pong wavefunctions (local)
    alignas(16) float fball[2][2][NPAD];  // ping-pong broadcast fb vectors (DSMEM-filled)
    alignas(16) float kin [RPAD][NPAD];
    alignas(16) float vint[RPAD][NPAD];
};

__device__ __forceinline__ uint32_t smem_u32(const void* p) {
    return (uint32_t)__cvta_generic_to_shared(p);
}
__device__ __forceinline__ void st_cluster_f32(uint32_t laddr, int rank, float v) {
    uint32_t r;
    asm volatile("mapa.shared::cluster.u32 %0, %1, %2;" : "=r"(r) : "r"(laddr), "r"(rank));
    asm volatile("st.shared::cluster.u32 [%0], %1;" :: "r"(r), "r"(__float_as_uint(v)) : "memory");
}
__device__ __forceinline__ void mbar_arrive_remote(uint32_t laddr, int rank) {
    asm volatile("{\n\t.reg .b32 ra;\n\t"
        "mapa.shared::cluster.u32 ra, %0, %1;\n\t"
        "mbarrier.arrive.release.cluster.shared::cluster.b64 _, [ra];\n\t}"
        :: "r"(laddr), "r"(rank) : "memory");
}
__device__ __forceinline__ void mbar_wait_parity(uint32_t addr, uint32_t parity) {
    uint32_t done;
    asm volatile("{\n\t.reg .pred p;\n\t"
        "mbarrier.try_wait.parity.acquire.cluster.shared::cta.b64 p, [%1], %2;\n\t"
        "selp.b32 %0, 1, 0, p;\n\t}"
        : "=r"(done) : "r"(addr), "r"(parity) : "memory");
    if (!done) {
        asm volatile("{\n\t.reg .pred P1;\n\t"
            "W_%=:\n\t"
            "mbarrier.try_wait.parity.acquire.cluster.shared::cta.b64 P1, [%0], %1, 0x989680;\n\t"
            "@P1 bra.uni D_%=;\n\t"
            "bra.uni W_%=;\n\t"
            "D_%=:\n\t}"
            :: "r"(addr), "r"(parity) : "memory");
    }
}
#define CLUSTER_SYNC() do { \
    asm volatile("barrier.cluster.arrive.aligned;" ::: "memory"); \
    asm volatile("barrier.cluster.wait.aligned;"   ::: "memory"); \
} while (0)

__device__ __forceinline__ float wred(float v) {     // full-warp sum
    v += __shfl_xor_sync(0xFFFFFFFFu, v, 16);
    v += __shfl_xor_sync(0xFFFFFFFFu, v, 8);
    v += __shfl_xor_sync(0xFFFFFFFFu, v, 4);
    v += __shfl_xor_sync(0xFFFFFFFFu, v, 2);
    v += __shfl_xor_sync(0xFFFFFFFFu, v, 1);
    return v;
}
__device__ __forceinline__ float gred(float v) {     // 8-lane group sum (all lanes get it)
    v += __shfl_xor_sync(0xFFFFFFFFu, v, 4);
    v += __shfl_xor_sync(0xFFFFFFFFu, v, 2);
    v += __shfl_xor_sync(0xFFFFFFFFu, v, 1);
    return v;
}

// ---- packed f32x2 helpers (FFMA2, PTX-only) ----
__device__ __forceinline__ ull mul2(ull a, ull b) {
    ull d; asm("mul.rn.f32x2 %0, %1, %2;" : "=l"(d) : "l"(a), "l"(b)); return d;
}
__device__ __forceinline__ ull fma2(ull a, ull b, ull c) {
    ull d; asm("fma.rn.f32x2 %0, %1, %2, %3;" : "=l"(d) : "l"(a), "l"(b), "l"(c)); return d;
}
__device__ __forceinline__ float hadd2(ull a) {
    uint32_t lo, hi;
    asm("mov.b64 {%0, %1}, %2;" : "=r"(lo), "=r"(hi) : "l"(a));
    return __uint_as_float(lo) + __uint_as_float(hi);
}
__device__ __forceinline__ void ld2x2(const float* p, int c1, int c2, ull* o) {
    ulonglong2 t0 = *reinterpret_cast<const ulonglong2*>(p + c1);
    ulonglong2 t1 = *reinterpret_cast<const ulonglong2*>(p + c2);
    o[0] = t0.x; o[1] = t0.y; o[2] = t1.x; o[3] = t1.y;
}
__device__ __forceinline__ float dot4p(const ull* k, const ull* x) {
    ull acc = mul2(k[0], x[0]);
    acc = fma2(k[1], x[1], acc);
    acc = fma2(k[2], x[2], acc);
    acc = fma2(k[3], x[3], acc);
    return hadd2(acc);
}
__device__ __forceinline__ float dot8f(float4 a0, float4 a1, float4 b0, float4 b1) {
    float s = a0.x * b0.x;
    s = fmaf(a0.y, b0.y, s); s = fmaf(a0.z, b0.z, s); s = fmaf(a0.w, b0.w, s);
    s = fmaf(a1.x, b1.x, s); s = fmaf(a1.y, b1.y, s);
    s = fmaf(a1.z, b1.z, s); s = fmaf(a1.w, b1.w, s);
    return s;
}

__global__ void __launch_bounds__(NTH, 1) __cluster_dims__(CN, 1, 1)
hf_kernel(const float* __restrict__ wfy0, const float* __restrict__ kin,
          const float* __restrict__ vint, const float* __restrict__ uho,
          const float* __restrict__ delx_p, const float* __restrict__ pfac_p,
          const int* __restrict__ iter_p, float* __restrict__ out)
{
    extern __shared__ char smraw[];
    Smem* s = reinterpret_cast<Smem*>(smraw);
    const int tid  = threadIdx.x;
    const int wid  = tid >> 5;
    const int lane = tid & 31;
    uint32_t rank;
    asm("mov.u32 %0, %%cluster_ctarank;" : "=r"(rank));
    const int row0 = (int)rank * RPC;
    const float delx = *delx_p;
    const float pfac = *pfac_p;
    const float rdelx = 1.f / delx;
    const int itermax = *iter_p;

    // ---- init ----
    if (tid == 0) {
        asm volatile("mbarrier.init.shared.b64 [%0], %1;" :: "r"(smem_u32(&s->mbar[0])), "r"(CN) : "memory");
        asm volatile("mbarrier.init.shared.b64 [%0], %1;" :: "r"(smem_u32(&s->mbar[1])), "r"(CN) : "memory");
    }
    for (int i = tid; i < RPAD * NPAD; i += NTH) {
        int r = i >> 8, c = i & 255;
        bool ok = (r < RPC) && (c < NXg);
        s->kin [r][c] = ok ? kin [(row0 + r) * NXg + c] : 0.f;
        s->vint[r][c] = ok ? vint[(row0 + r) * NXg + c] : 0.f;
    }
    for (int c = tid; c < NPAD; c += NTH) {
        float a = (c < NXg) ? wfy0[c * 2 + 0] : 0.f;
        float b = (c < NXg) ? wfy0[c * 2 + 1] : 0.f;
        s->wbuf[0][0][c] = a;   s->wbuf[0][1][c] = b;
        s->wbuf[1][0][c] = 0.f; s->wbuf[1][1][c] = 0.f;
        s->fball[0][0][c] = 0.f; s->fball[0][1][c] = 0.f;
        s->fball[1][0][c] = 0.f; s->fball[1][1][c] = 0.f;
        s->uho[c] = (c < NXg) ? uho[c] : 0.f;
    }
    __syncthreads();
    CLUSTER_SYNC();   // mbar init + zero padding visible cluster-wide

    const int m = lane & 7;            // column-slice owner within 8-lane group
    const int g = lane >> 3;           // row group within warp
    const int row  = (wid << 2) + g;   // 0..31 (30,31 padded-zero rows)
    const int gi   = row0 + row;
    const bool active = row < RPC;
    const int c1 = lane * 4;           // for warp-wide dots (scalar phase / epilogue)
    const int c2 = 128 + lane * 4;

    for (int it = 0; it < itermax; ++it) {
        const int cur = it & 1, nx = cur ^ 1;
        const float* w0 = s->wbuf[cur][0];
        const float* w1 = s->wbuf[cur][1];

        // ---- matvec: row per 8-lane group, lane m owns cols m*4 + j*32 ----
        ull kw0 = 0, kw1 = 0, v00 = 0, v01 = 0, v11 = 0;
        const float* kr = s->kin[row];
        const float* vr = s->vint[row];
        #pragma unroll
        for (int j = 0; j < 8; ++j) {
            int c = m * 4 + j * 32;
            ulonglong2 K = *(const ulonglong2*)(kr + c);
            ulonglong2 V = *(const ulonglong2*)(vr + c);
            ulonglong2 Aq = *(const ulonglong2*)(w0 + c);
            ulonglong2 Bq = *(const ulonglong2*)(w1 + c);
            kw0 = fma2(K.x, Aq.x, kw0); kw0 = fma2(K.y, Aq.y, kw0);
            kw1 = fma2(K.x, Bq.x, kw1); kw1 = fma2(K.y, Bq.y, kw1);
            v00 = fma2(V.x, mul2(Aq.x, Aq.x), v00); v00 = fma2(V.y, mul2(Aq.y, Aq.y), v00);
            v01 = fma2(V.x, mul2(Aq.x, Bq.x), v01); v01 = fma2(V.y, mul2(Aq.y, Bq.y), v01);
            v11 = fma2(V.x, mul2(Bq.x, Bq.x), v11); v11 = fma2(V.y, mul2(Bq.y, Bq.y), v11);
        }
        float skw0 = gred(hadd2(kw0));
        float skw1 = gred(hadd2(kw1));
        float sv00 = gred(hadd2(v00));
        float sv01 = gred(hadd2(v01));
        float sv11 = gred(hadd2(v11));

        // all 8 lanes of the group redundantly finish the row; lane m -> rank m
        {
            float w0i = w0[gi], w1i = w1[gi], uh = s->uho[gi];
            float ud  = delx * (sv00 + sv11);
            float hw0 = skw0 - delx * (w0i * sv00 + w1i * sv01) + (ud + uh) * w0i;
            float hw1 = skw1 - delx * (w0i * sv01 + w1i * sv11) + (ud + uh) * w1i;
            float fb0 = w0i - pfac * hw0;
            float fb1 = w1i - pfac * hw1;
            if (active) {
                if (m == 0) s->udirs[row] = ud;
                st_cluster_f32(smem_u32(&s->fball[cur][0][gi]), m, fb0);
                st_cluster_f32(smem_u32(&s->fball[cur][1][gi]), m, fb1);
            }
        }
        __syncthreads();                                  // barA: all scatters issued
        if (tid < CN) mbar_arrive_remote(smem_u32(&s->mbar[cur]), tid);
        mbar_wait_parity(smem_u32(&s->mbar[cur]), (uint32_t)((it >> 1) & 1));

        // ---- 9 global scalars, one warp each, from full fb + local w ----
        {
            const float* f0a = s->fball[cur][0];
            const float* f1a = s->fball[cur][1];
            const float* xs; const float* ys;
            switch (wid) {
                case 0:  xs = f0a; ys = f0a; break;   // S0
                case 1:  xs = f1a; ys = f1a; break;   // S1
                case 2:  xs = f0a; ys = f1a; break;   // Xs
                case 3:  xs = w0;  ys = f1a; break;   // Ys
                case 4:  xs = f0a; ys = w0;  break;   // Zs
                case 5:  xs = w0;  ys = w0;  break;   // W2
                case 6:  xs = w1;  ys = w1;  break;   // V2
                default: xs = w1;  ys = f1a; break;   // Us
            }
            float4 X0 = *(const float4*)(xs + c1), X1 = *(const float4*)(xs + c2);
            float4 Y0 = *(const float4*)(ys + c1), Y1 = *(const float4*)(ys + c2);
            float v = dot8f(X0, X1, Y0, Y1);
            v = wred(v);
            if (lane == 0) s->scal[wid] = v;
            if (wid == 0) {   // EH = sum (w0^2 + w1^2) * uho
                float4 P0 = *(const float4*)(w0 + c1), P1 = *(const float4*)(w0 + c2);
                float4 Q0 = *(const float4*)(w1 + c1), Q1 = *(const float4*)(w1 + c2);
                float4 U0 = *(const float4*)(s->uho + c1), U1 = *(const float4*)(s->uho + c2);
                float e = (P0.x*P0.x + Q0.x*Q0.x) * U0.x;
                e = fmaf(P0.y*P0.y + Q0.y*Q0.y, U0.y, e);
                e = fmaf(P0.z*P0.z + Q0.z*Q0.z, U0.z, e);
                e = fmaf(P0.w*P0.w + Q0.w*Q0.w, U0.w, e);
                e = fmaf(P1.x*P1.x + Q1.x*Q1.x, U1.x, e);
                e = fmaf(P1.y*P1.y + Q1.y*Q1.y, U1.y, e);
                e = fmaf(P1.z*P1.z + Q1.z*Q1.z, U1.z, e);
                e = fmaf(P1.w*P1.w + Q1.w*Q1.w, U1.w, e);
                e = wred(e);
                if (lane == 0) s->scal[8] = e;
            }
        }
        __syncthreads();                                  // barB: scalars ready

        // ---- update: every element thread, closed-form chain redundant ----
        if (tid < NXg) {
            float S0 = s->scal[0], S1 = s->scal[1], Xs = s->scal[2];
            float Ys = s->scal[3], Zs = s->scal[4], W2 = s->scal[5];
            float inv0 = rsqrtf(S0 * delx);
            float inv1 = rsqrtf(S1 * delx);
            float dGS  = FFACf * inv0 * inv1 * Xs + OMFf * inv1 * Ys;
            float sn0  = 0.16f * rdelx + 0.48f * inv0 * Zs + 0.36f * W2;
            float T1   = rdelx - dGS * dGS * delx * (2.f - delx * sn0);
            float invT1d = __fdividef(1.f, T1 * delx);
            float a0 = FFACf * inv0;
            float b1 = FFACf * invT1d * inv1;
            float cc = FFACf * invT1d * dGS * delx;
            float fb0 = s->fball[cur][0][tid];
            float fb1 = s->fball[cur][1][tid];
            float n0 = a0 * fb0 + OMFf * w0[tid];
            float n1 = b1 * fb1 - cc * n0 + OMFf * w1[tid];
            s->wbuf[nx][0][tid] = n0;
            s->wbuf[nx][1][tid] = n1;
        }
        __syncthreads();                                  // barC: wbuf[nx] ready
    }

    // ---- final energies: ekin = new.K.new, epot = new.Umf.new ----
    {
        const int fin = itermax & 1, oldp = fin ^ 1;
        const float* wo0 = s->wbuf[oldp][0]; const float* wo1 = s->wbuf[oldp][1];
        const float* nv0 = s->wbuf[fin][0];  const float* nv1 = s->wbuf[fin][1];
        ull Ao[4], Bo[4], N0[4], N1[4], P0[4], P1[4], Q0[4], Q1[4];
        ld2x2(wo0, c1, c2, Ao);
        ld2x2(wo1, c1, c2, Bo);
        ld2x2(nv0, c1, c2, N0);
        ld2x2(nv1, c1, c2, N1);
        #pragma unroll
        for (int i = 0; i < 4; ++i) {
            P0[i] = mul2(Ao[i], N0[i]);
            P1[i] = mul2(Bo[i], N0[i]);
            Q0[i] = mul2(Ao[i], N1[i]);
            Q1[i] = mul2(Bo[i], N1[i]);
        }
        float pek = 0.f, pep = 0.f;
        for (int r = wid; r < RPC; r += NW) {
            ull K[4], V[4];
            ld2x2(s->kin[r],  c1, c2, K);
            ld2x2(s->vint[r], c1, c2, V);
            float kn0 = dot4p(K, N0), kn1 = dot4p(K, N1);
            float q00 = dot4p(V, P0), q10 = dot4p(V, P1);
            float q01 = dot4p(V, Q0), q11 = dot4p(V, Q1);
            kn0 = wred(kn0); kn1 = wred(kn1);
            q00 = wred(q00); q10 = wred(q10);
            q01 = wred(q01); q11 = wred(q11);
            if (lane == 0) {
                int gr = row0 + r;
                float n0i = nv0[gr], n1i = nv1[gr];
                float w0o = wo0[gr], w1o = wo1[gr];
                float diag = s->udirs[r] + s->uho[gr];
                float um0 = -delx * (w0o * q00 + w1o * q10) + diag * n0i;
                float um1 = -delx * (w0o * q01 + w1o * q11) + diag * n1i;
                pek += n0i * kn0 + n1i * kn1;
                pep += n0i * um0 + n1i * um1;
            }
        }
        if (lane == 0) { s->wred2[wid][0] = pek; s->wred2[wid][1] = pep; }
        __syncthreads();
        if (tid < 2) {
            float v = 0.f;
            #pragma unroll
            for (int w = 0; w < NW; ++w) v += s->wred2[w][tid];
            uint32_t la = smem_u32(&s->redF[rank][tid]);
            #pragma unroll
            for (int tr = 0; tr < CN; ++tr) st_cluster_f32(la, tr, v);
        }
        CLUSTER_SYNC();
        if (rank == 0 && tid == 0) {
            float EK = 0.f, EP = 0.f;
            for (int rr = 0; rr < CN; ++rr) { EK += s->redF[rr][0]; EP += s->redF[rr][1]; }
            // last-iteration scalars are replicated in every CTA's s->scal
            float Zs = s->scal[4], W2 = s->scal[5], V2 = s->scal[6];
            float Us = s->scal[7], EH = s->scal[8];
            float esum = ((W2 - Zs) + (V2 - Us)) / pfac * delx;
            float eho  = EH * delx * 0.5f;
            float ekin = EK * delx;
            float epot = EP * delx;
            float enerhfp = (esum + ekin) * 0.5f + eho;
            float epot0   = epot - 2.f * eho;
            float enerhf  = esum - epot0 * 0.5f;
            out[0] = enerhf; out[1] = enerhfp; out[2] = ekin;
            out[3] = eho;    out[4] = epot0;   out[5] = esum;
        }
    }
}

extern "C" void kernel_launch(void* const* d_in, const int* in_sizes, int n_in,
                              void* d_out, int out_size) {
    (void)in_sizes; (void)n_in; (void)out_size;
    cudaFuncSetAttribute(hf_kernel, cudaFuncAttributeMaxDynamicSharedMemorySize,
                         (int)sizeof(Smem));
    hf_kernel<<<CN, NTH, sizeof(Smem)>>>(
        (const float*)d_in[0],   // wfy0 (240,2)
        (const float*)d_in[1],   // kin_mat (240,240)
        (const float*)d_in[2],   // Vint (240,240)
        (const float*)d_in[3],   // U_HO (240)
        (const float*)d_in[4],   // delx
        (const float*)d_in[5],   // pfac
        (const int*)d_in[6],     // itermax
        (float*)d_out);          // 6 outputs
}

// round 7
// speedup vs baseline: 1.2442x; 1.0051x over previous
#include <cuda_runtime.h>
#include <cstdint>

#define NXg   240
#define NPAD  256
#define CN    8      // cluster size (CTAs)
#define RPC   30     // rows per CTA
#define RPAD  32     // padded row count (rows 30,31 zero)
#define NTH   256    // 8 warps
#define NW    8
#define FFACf 0.4f
#define OMFf  0.6f

typedef unsigned long long ull;

struct __align__(16) Smem {
    alignas(16) ull   mbar[2];            // ping-pong cluster barriers (count=8)
    alignas(16) float scal[12];           // 9 global scalars (per-CTA replicated)
    alignas(16) float udirs[32];
    alignas(16) float wred2[NW][2];
    alignas(16) float redF[CN][2];        // final-energy cluster slots
    alignas(16) float uho [NPAD];
    alignas(16) float wbuf [2][2][NPAD];  // ping-pong wavefunctions (local)
    alignas(16) float fball[2][2][NPAD];  // ping-pong broadcast fb vectors (DSMEM-filled)
    alignas(16) float kin [RPAD][NPAD];
    alignas(16) float vint[RPAD][NPAD];
};

__device__ __forceinline__ uint32_t smem_u32(const void* p) {
    return (uint32_t)__cvta_generic_to_shared(p);
}
__device__ __forceinline__ uint32_t mapa_u32(uint32_t laddr, int rank) {
    uint32_t r;
    asm("mapa.shared::cluster.u32 %0, %1, %2;" : "=r"(r) : "r"(laddr), "r"(rank));
    return r;
}
__device__ __forceinline__ void st_remote_f32(uint32_t raddr, float v) {
    asm volatile("st.shared::cluster.u32 [%0], %1;" :: "r"(raddr), "r"(__float_as_uint(v)) : "memory");
}
__device__ __forceinline__ void st_cluster_f32(uint32_t laddr, int rank, float v) {
    st_remote_f32(mapa_u32(laddr, rank), v);
}
__device__ __forceinline__ void mbar_arrive_remote(uint32_t laddr, int rank) {
    asm volatile("{\n\t.reg .b32 ra;\n\t"
        "mapa.shared::cluster.u32 ra, %0, %1;\n\t"
        "mbarrier.arrive.release.cluster.shared::cluster.b64 _, [ra];\n\t}"
        :: "r"(laddr), "r"(rank) : "memory");
}
__device__ __forceinline__ void mbar_wait_parity(uint32_t addr, uint32_t parity) {
    uint32_t done;
    asm volatile("{\n\t.reg .pred p;\n\t"
        "mbarrier.try_wait.parity.acquire.cluster.shared::cta.b64 p, [%1], %2;\n\t"
        "selp.b32 %0, 1, 0, p;\n\t}"
        : "=r"(done) : "r"(addr), "r"(parity) : "memory");
    if (!done) {
        asm volatile("{\n\t.reg .pred P1;\n\t"
            "W_%=:\n\t"
            "mbarrier.try_wait.parity.acquire.cluster.shared::cta.b64 P1, [%0], %1, 0x989680;\n\t"
            "@P1 bra.uni D_%=;\n\t"
            "bra.uni W_%=;\n\t"
            "D_%=:\n\t}"
            :: "r"(addr), "r"(parity) : "memory");
    }
}
#define CLUSTER_SYNC() do { \
    asm volatile("barrier.cluster.arrive.aligned;" ::: "memory"); \
    asm volatile("barrier.cluster.wait.aligned;"   ::: "memory"); \
} while (0)

__device__ __forceinline__ float wred(float v) {     // full-warp sum
    v += __shfl_xor_sync(0xFFFFFFFFu, v, 16);
    v += __shfl_xor_sync(0xFFFFFFFFu, v, 8);
    v += __shfl_xor_sync(0xFFFFFFFFu, v, 4);
    v += __shfl_xor_sync(0xFFFFFFFFu, v, 2);
    v += __shfl_xor_sync(0xFFFFFFFFu, v, 1);
    return v;
}
__device__ __forceinline__ float gred(float v) {     // 8-lane group sum (all lanes get it)
    v += __shfl_xor_sync(0xFFFFFFFFu, v, 4);
    v += __shfl_xor_sync(0xFFFFFFFFu, v, 2);
    v += __shfl_xor_sync(0xFFFFFFFFu, v, 1);
    return v;
}

// ---- packed f32x2 helpers (FFMA2, PTX-only) ----
__device__ __forceinline__ ull mul2(ull a, ull b) {
    ull d; asm("mul.rn.f32x2 %0, %1, %2;" : "=l"(d) : "l"(a), "l"(b)); return d;
}
__device__ __forceinline__ ull fma2(ull a, ull b, ull c) {
    ull d; asm("fma.rn.f32x2 %0, %1, %2, %3;" : "=l"(d) : "l"(a), "l"(b), "l"(c)); return d;
}
__device__ __forceinline__ float hadd2(ull a) {
    uint32_t lo, hi;
    asm("mov.b64 {%0, %1}, %2;" : "=r"(lo), "=r"(hi) : "l"(a));
    return __uint_as_float(lo) + __uint_as_float(hi);
}
__device__ __forceinline__ void ld2x2(const float* p, int c1, int c2, ull* o) {
    ulonglong2 t0 = *reinterpret_cast<const ulonglong2*>(p + c1);
    ulonglong2 t1 = *reinterpret_cast<const ulonglong2*>(p + c2);
    o[0] = t0.x; o[1] = t0.y; o[2] = t1.x; o[3] = t1.y;
}
__device__ __forceinline__ float dot4p(const ull* k, const ull* x) {
    ull acc = mul2(k[0], x[0]);
    acc = fma2(k[1], x[1], acc);
    acc = fma2(k[2], x[2], acc);
    acc = fma2(k[3], x[3], acc);
    return hadd2(acc);
}
__device__ __forceinline__ float dot8f(float4 a0, float4 a1, float4 b0, float4 b1) {
    float s = a0.x * b0.x;
    s = fmaf(a0.y, b0.y, s); s = fmaf(a0.z, b0.z, s); s = fmaf(a0.w, b0.w, s);
    s = fmaf(a1.x, b1.x, s); s = fmaf(a1.y, b1.y, s);
    s = fmaf(a1.z, b1.z, s); s = fmaf(a1.w, b1.w, s);
    return s;
}

__global__ void __launch_bounds__(NTH, 1) __cluster_dims__(CN, 1, 1)
hf_kernel(const float* __restrict__ wfy0, const float* __restrict__ kin,
          const float* __restrict__ vint, const float* __restrict__ uho,
          const float* __restrict__ delx_p, const float* __restrict__ pfac_p,
          const int* __restrict__ iter_p, float* __restrict__ out)
{
    extern __shared__ char smraw[];
    Smem* s = reinterpret_cast<Smem*>(smraw);
    const int tid  = threadIdx.x;
    const int wid  = tid >> 5;
    const int lane = tid & 31;
    uint32_t rank;
    asm("mov.u32 %0, %%cluster_ctarank;" : "=r"(rank));
    const int row0 = (int)rank * RPC;
    const float delx = *delx_p;
    const float pfac = *pfac_p;
    const float rdelx = 1.f / delx;
    const int itermax = *iter_p;

    // ---- init ----
    if (tid == 0) {
        asm volatile("mbarrier.init.shared.b64 [%0], %1;" :: "r"(smem_u32(&s->mbar[0])), "r"(CN) : "memory");
        asm volatile("mbarrier.init.shared.b64 [%0], %1;" :: "r"(smem_u32(&s->mbar[1])), "r"(CN) : "memory");
    }
    for (int i = tid; i < RPAD * NPAD; i += NTH) {
        int r = i >> 8, c = i & 255;
        bool ok = (r < RPC) && (c < NXg);
        s->kin [r][c] = ok ? kin [(row0 + r) * NXg + c] : 0.f;
        s->vint[r][c] = ok ? vint[(row0 + r) * NXg + c] : 0.f;
    }
    for (int c = tid; c < NPAD; c += NTH) {
        float a = (c < NXg) ? wfy0[c * 2 + 0] : 0.f;
        float b = (c < NXg) ? wfy0[c * 2 + 1] : 0.f;
        s->wbuf[0][0][c] = a;   s->wbuf[0][1][c] = b;
        s->wbuf[1][0][c] = 0.f; s->wbuf[1][1][c] = 0.f;
        s->fball[0][0][c] = 0.f; s->fball[0][1][c] = 0.f;
        s->fball[1][0][c] = 0.f; s->fball[1][1][c] = 0.f;
        s->uho[c] = (c < NXg) ? uho[c] : 0.f;
    }
    __syncthreads();
    CLUSTER_SYNC();   // mbar init + zero padding visible cluster-wide

    const int m = lane & 7;            // column-slice owner within 8-lane group
    const int g = lane >> 3;           // row group within warp
    const int row  = (wid << 2) + g;   // 0..31 (30,31 padded-zero rows)
    const int gi   = row0 + row;
    const bool active = row < RPC;
    const int c1 = lane * 4;           // for warp-wide dots (scalar phase / epilogue)
    const int c2 = 128 + lane * 4;

    // hoisted remote scatter addresses (per parity, target rank = m)
    uint32_t ra0[2], ra1[2];
    #pragma unroll
    for (int p = 0; p < 2; ++p) {
        ra0[p] = mapa_u32(smem_u32(&s->fball[p][0][gi]), m);
        ra1[p] = mapa_u32(smem_u32(&s->fball[p][1][gi]), m);
    }

    for (int it = 0; it < itermax; ++it) {
        const int cur = it & 1, nx = cur ^ 1;
        const float* w0 = s->wbuf[cur][0];
        const float* w1 = s->wbuf[cur][1];

        // ---- RHS vectors in registers (same columns for all groups) ----
        ull A[16], B[16];
        #pragma unroll
        for (int j = 0; j < 8; ++j) {
            int c = m * 4 + j * 32;
            ulonglong2 ta = *(const ulonglong2*)(w0 + c);
            ulonglong2 tb = *(const ulonglong2*)(w1 + c);
            A[2*j] = ta.x; A[2*j+1] = ta.y;
            B[2*j] = tb.x; B[2*j+1] = tb.y;
        }

        // ---- matvec: row per 8-lane group; only K,V touched in SMEM ----
        ull kw0 = 0, kw1 = 0, v00 = 0, v01 = 0, v11 = 0;
        const float* kr = s->kin[row];
        const float* vr = s->vint[row];
        #pragma unroll
        for (int j = 0; j < 8; ++j) {
            int c = m * 4 + j * 32;
            ulonglong2 K = *(const ulonglong2*)(kr + c);
            ulonglong2 V = *(const ulonglong2*)(vr + c);
            ull a0 = A[2*j], a1 = A[2*j+1];
            ull b0 = B[2*j], b1 = B[2*j+1];
            kw0 = fma2(K.x, a0, kw0); kw0 = fma2(K.y, a1, kw0);
            kw1 = fma2(K.x, b0, kw1); kw1 = fma2(K.y, b1, kw1);
            v00 = fma2(V.x, mul2(a0, a0), v00); v00 = fma2(V.y, mul2(a1, a1), v00);
            v01 = fma2(V.x, mul2(a0, b0), v01); v01 = fma2(V.y, mul2(a1, b1), v01);
            v11 = fma2(V.x, mul2(b0, b0), v11); v11 = fma2(V.y, mul2(b1, b1), v11);
        }
        float skw0 = gred(hadd2(kw0));
        float skw1 = gred(hadd2(kw1));
        float sv00 = gred(hadd2(v00));
        float sv01 = gred(hadd2(v01));
        float sv11 = gred(hadd2(v11));

        // all 8 lanes of the group redundantly finish the row; lane m -> rank m
        {
            float w0i = w0[gi], w1i = w1[gi], uh = s->uho[gi];
            float ud  = delx * (sv00 + sv11);
            float hw0 = skw0 - delx * (w0i * sv00 + w1i * sv01) + (ud + uh) * w0i;
            float hw1 = skw1 - delx * (w0i * sv01 + w1i * sv11) + (ud + uh) * w1i;
            float fb0 = w0i - pfac * hw0;
            float fb1 = w1i - pfac * hw1;
            if (active) {
                if (m == 0) s->udirs[row] = ud;
                st_remote_f32(ra0[cur], fb0);
                st_remote_f32(ra1[cur], fb1);
            }
        }
        __syncthreads();                                  // barA: all scatters issued
        if (tid < CN) mbar_arrive_remote(smem_u32(&s->mbar[cur]), tid);
        mbar_wait_parity(smem_u32(&s->mbar[cur]), (uint32_t)((it >> 1) & 1));

        // ---- 9 global scalars, one warp each, from full fb + local w ----
        {
            const float* f0a = s->fball[cur][0];
            const float* f1a = s->fball[cur][1];
            const float* xs; const float* ys;
            switch (wid) {
                case 0:  xs = f0a; ys = f0a; break;   // S0
                case 1:  xs = f1a; ys = f1a; break;   // S1
                case 2:  xs = f0a; ys = f1a; break;   // Xs
                case 3:  xs = w0;  ys = f1a; break;   // Ys
                case 4:  xs = f0a; ys = w0;  break;   // Zs
                case 5:  xs = w0;  ys = w0;  break;   // W2
                case 6:  xs = w1;  ys = w1;  break;   // V2
                default: xs = w1;  ys = f1a; break;   // Us
            }
            float4 X0 = *(const float4*)(xs + c1), X1 = *(const float4*)(xs + c2);
            float4 Y0 = *(const float4*)(ys + c1), Y1 = *(const float4*)(ys + c2);
            float v = dot8f(X0, X1, Y0, Y1);
            v = wred(v);
            if (lane == 0) s->scal[wid] = v;
            if (wid == 0) {   // EH = sum (w0^2 + w1^2) * uho
                float4 P0 = *(const float4*)(w0 + c1), P1 = *(const float4*)(w0 + c2);
                float4 Q0 = *(const float4*)(w1 + c1), Q1 = *(const float4*)(w1 + c2);
                float4 U0 = *(const float4*)(s->uho + c1), U1 = *(const float4*)(s->uho + c2);
                float e = (P0.x*P0.x + Q0.x*Q0.x) * U0.x;
                e = fmaf(P0.y*P0.y + Q0.y*Q0.y, U0.y, e);
                e = fmaf(P0.z*P0.z + Q0.z*Q0.z, U0.z, e);
                e = fmaf(P0.w*P0.w + Q0.w*Q0.w, U0.w, e);
                e = fmaf(P1.x*P1.x + Q1.x*Q1.x, U1.x, e);
                e = fmaf(P1.y*P1.y + Q1.y*Q1.y, U1.y, e);
                e = fmaf(P1.z*P1.z + Q1.z*Q1.z, U1.z, e);
                e = fmaf(P1.w*P1.w + Q1.w*Q1.w, U1.w, e);
                e = wred(e);
                if (lane == 0) s->scal[8] = e;
            }
        }
        __syncthreads();                                  // barB: scalars ready

        // ---- update: every element thread, closed-form chain redundant ----
        if (tid < NXg) {
            float S0 = s->scal[0], S1 = s->scal[1], Xs = s->scal[2];
            float Ys = s->scal[3], Zs = s->scal[4], W2 = s->scal[5];
            float inv0 = rsqrtf(S0 * delx);
            float inv1 = rsqrtf(S1 * delx);
            float dGS  = FFACf * inv0 * inv1 * Xs + OMFf * inv1 * Ys;
            float sn0  = 0.16f * rdelx + 0.48f * inv0 * Zs + 0.36f * W2;
            float T1   = rdelx - dGS * dGS * delx * (2.f - delx * sn0);
            float invT1d = __fdividef(1.f, T1 * delx);
            float a0 = FFACf * inv0;
            float b1 = FFACf * invT1d * inv1;
            float cc = FFACf * invT1d * dGS * delx;
            float fb0 = s->fball[cur][0][tid];
            float fb1 = s->fball[cur][1][tid];
            float n0 = a0 * fb0 + OMFf * w0[tid];
            float n1 = b1 * fb1 - cc * n0 + OMFf * w1[tid];
            s->wbuf[nx][0][tid] = n0;
            s->wbuf[nx][1][tid] = n1;
        }
        __syncthreads();                                  // barC: wbuf[nx] ready
    }

    // ---- final energies: ekin = new.K.new, epot = new.Umf.new ----
    {
        const int fin = itermax & 1, oldp = fin ^ 1;
        const float* wo0 = s->wbuf[oldp][0]; const float* wo1 = s->wbuf[oldp][1];
        const float* nv0 = s->wbuf[fin][0];  const float* nv1 = s->wbuf[fin][1];
        ull Ao[4], Bo[4], N0[4], N1[4], P0[4], P1[4], Q0[4], Q1[4];
        ld2x2(wo0, c1, c2, Ao);
        ld2x2(wo1, c1, c2, Bo);
        ld2x2(nv0, c1, c2, N0);
        ld2x2(nv1, c1, c2, N1);
        #pragma unroll
        for (int i = 0; i < 4; ++i) {
            P0[i] = mul2(Ao[i], N0[i]);
            P1[i] = mul2(Bo[i], N0[i]);
            Q0[i] = mul2(Ao[i], N1[i]);
            Q1[i] = mul2(Bo[i], N1[i]);
        }
        float pek = 0.f, pep = 0.f;
        for (int r = wid; r < RPC; r += NW) {
            ull K[4], V[4];
            ld2x2(s->kin[r],  c1, c2, K);
            ld2x2(s->vint[r], c1, c2, V);
            float kn0 = dot4p(K, N0), kn1 = dot4p(K, N1);
            float q00 = dot4p(V, P0), q10 = dot4p(V, P1);
            float q01 = dot4p(V, Q0), q11 = dot4p(V, Q1);
            kn0 = wred(kn0); kn1 = wred(kn1);
            q00 = wred(q00); q10 = wred(q10);
            q01 = wred(q01); q11 = wred(q11);
            if (lane == 0) {
                int gr = row0 + r;
                float n0i = nv0[gr], n1i = nv1[gr];
                float w0o = wo0[gr], w1o = wo1[gr];
                float diag = s->udirs[r] + s->uho[gr];
                float um0 = -delx * (w0o * q00 + w1o * q10) + diag * n0i;
                float um1 = -delx * (w0o * q01 + w1o * q11) + diag * n1i;
                pek += n0i * kn0 + n1i * kn1;
                pep += n0i * um0 + n1i * um1;
            }
        }
        if (lane == 0) { s->wred2[wid][0] = pek; s->wred2[wid][1] = pep; }
        __syncthreads();
        if (tid < 2) {
            float v = 0.f;
            #pragma unroll
            for (int w = 0; w < NW; ++w) v += s->wred2[w][tid];
            uint32_t la = smem_u32(&s->redF[rank][tid]);
            #pragma unroll
            for (int tr = 0; tr < CN; ++tr) st_cluster_f32(la, tr, v);
        }
        CLUSTER_SYNC();
        if (rank == 0 && tid == 0) {
            float EK = 0.f, EP = 0.f;
            for (int rr = 0; rr < CN; ++rr) { EK += s->redF[rr][0]; EP += s->redF[rr][1]; }
            // last-iteration scalars are replicated in every CTA's s->scal
            float Zs = s->scal[4], W2 = s->scal[5], V2 = s->scal[6];
            float Us = s->scal[7], EH = s->scal[8];
            float esum = ((W2 - Zs) + (V2 - Us)) / pfac * delx;
            float eho  = EH * delx * 0.5f;
            float ekin = EK * delx;
            float epot = EP * delx;
            float enerhfp = (esum + ekin) * 0.5f + eho;
            float epot0   = epot - 2.f * eho;
            float enerhf  = esum - epot0 * 0.5f;
            out[0] = enerhf; out[1] = enerhfp; out[2] = ekin;
            out[3] = eho;    out[4] = epot0;   out[5] = esum;
        }
    }
}

extern "C" void kernel_launch(void* const* d_in, const int* in_sizes, int n_in,
                              void* d_out, int out_size) {
    (void)in_sizes; (void)n_in; (void)out_size;
    cudaFuncSetAttribute(hf_kernel, cudaFuncAttributeMaxDynamicSharedMemorySize,
                         (int)sizeof(Smem));
    hf_kernel<<<CN, NTH, sizeof(Smem)>>>(
        (const float*)d_in[0],   // wfy0 (240,2)
        (const float*)d_in[1],   // kin_mat (240,240)
        (const float*)d_in[2],   // Vint (240,240)
        (const float*)d_in[3],   // U_HO (240)
        (const float*)d_in[4],   // delx
        (const float*)d_in[5],   // pfac
        (const int*)d_in[6],     // itermax
        (float*)d_out);          // 6 outputs
}